// round 15
// baseline (speedup 1.0000x reference)
#include <cuda_runtime.h>
#include <cstdint>
#include <cstddef>

// ---------------------------------------------------------------------------
// LongTermMemoryMLP on sm_103 (legacy tensor path; tcgen05 blocked by the
// harness's compute_103 virtual arch).
// Round 15: BM=128 BN=256 BK=32, 256 thr, warp tile 64x64, m16n8k8.tf32,
// k8-granular frag pipeline (as round 14), PLUS:
//   * rna->tf32 rounding folded into fragment registers (1 cvt per reg after
//     LDSM) -> the 268MB pre-round pass and its scratch buffers are deleted.
//     Numerics identical: MMA truncation of an rna-rounded value == pre-round.
//   L0: [4096x512] @ [1024x512]^T  +b relu   (x8 batches)
//   L1: [4096x1024]@ [1024x1024]^T +b relu
//   L2: [4096x1024]@ [512x1024]^T  +b
// ---------------------------------------------------------------------------

#define BM 128
#define BN 256
#define BK 32
#define NSTAGE 4

#define ROWB 144                        // 128B k-data + 16B pad per smem row
#define A_BYTES (BM * ROWB)             // 18432
#define B_BYTES (BN * ROWB)             // 36864
#define STAGE_SZ (A_BYTES + B_BYTES)    // 55296
#define SMEM_BYTES (NSTAGE * STAGE_SZ)  // 221184

// ---------------- scratch (no allocations allowed) ----------------
__device__ float g_h0[8u * 4096u * 1024u];   // raw f32 activations (rounded at load)
__device__ float g_h1[8u * 4096u * 1024u];

// ---------------- helpers ----------------
__device__ __forceinline__ uint32_t smem_u32(const void* p) {
    uint32_t a;
    asm("{ .reg .u64 t; cvta.to.shared.u64 t, %1; cvt.u32.u64 %0, t; }" : "=r"(a) : "l"(p));
    return a;
}
__device__ __forceinline__ uint32_t f2tf(float x) {
    uint32_t r;
    asm("cvt.rna.tf32.f32 %0, %1;" : "=r"(r) : "f"(x));
    return r;
}
__device__ __forceinline__ void cp16(uint32_t dst, const void* src) {
    asm volatile("cp.async.cg.shared.global [%0], [%1], 16;" :: "r"(dst), "l"(src) : "memory");
}
__device__ __forceinline__ void ldsm4(uint32_t* r, uint32_t addr) {
    asm volatile("ldmatrix.sync.aligned.m8n8.x4.shared.b16 {%0,%1,%2,%3}, [%4];"
                 : "=r"(r[0]), "=r"(r[1]), "=r"(r[2]), "=r"(r[3]) : "r"(addr));
}
// rna-round the 4 regs of one ldmatrix result (each reg = one f32 operand)
__device__ __forceinline__ void rnd4(uint32_t* r) {
    r[0] = f2tf(__uint_as_float(r[0]));
    r[1] = f2tf(__uint_as_float(r[1]));
    r[2] = f2tf(__uint_as_float(r[2]));
    r[3] = f2tf(__uint_as_float(r[3]));
}
__device__ __forceinline__ void mma8(float* acc, const uint32_t* a, uint32_t b0, uint32_t b1) {
    asm("mma.sync.aligned.m16n8k8.row.col.f32.tf32.tf32.f32 "
        "{%0,%1,%2,%3}, {%4,%5,%6,%7}, {%8,%9}, {%0,%1,%2,%3};"
        : "+f"(acc[0]), "+f"(acc[1]), "+f"(acc[2]), "+f"(acc[3])
        : "r"(a[0]), "r"(a[1]), "r"(a[2]), "r"(a[3]), "r"(b0), "r"(b1));
}

// ---------------- main GEMM kernel ----------------
template <int KDIM, bool RELU>
__global__ __launch_bounds__(256, 1)
void gemm_tf32_pipe(const float* __restrict__ A,     // [B*4096, KDIM] raw f32
                    const float* __restrict__ W,     // [B*N,    KDIM] raw f32
                    const float* __restrict__ bias,  // [B*N]
                    float* __restrict__ C,           // [B*4096, N]
                    int N) {
    extern __shared__ char smem[];
    const uint32_t sb = smem_u32(smem);

    const int tid  = threadIdx.x;
    const int lane = tid & 31;
    const int warp = tid >> 5;
    const int wm   = (warp & 1) * 64;
    const int wn   = (warp >> 1) * 64;

    const int bz  = blockIdx.z;
    const int m0g = bz * 4096 + blockIdx.x * BM;
    const int n0  = blockIdx.y * BN;
    const int n0g = bz * N + n0;

    const float* At = A + (size_t)m0g * KDIM;
    const float* Wt = W + (size_t)n0g * KDIM;

    // cp.async mapping: rows have 8 chunks of 16B. 256 threads.
    const int arow0 = tid >> 3;          // 0..31
    const int akc   = tid & 7;
    const uint32_t acd = (uint32_t)arow0 * ROWB + akc * 16;
    const size_t   acs = (size_t)arow0 * KDIM + akc * 4;

    // ldmatrix base addresses (conflict-free under 144B row stride)
    const uint32_t aoff = (uint32_t)(wm + ((lane >> 3) & 1) * 8 + (lane & 7)) * ROWB
                        + (lane >> 4) * 16;
    const uint32_t boff = A_BYTES
                        + (uint32_t)(wn + (lane >> 4) * 8 + (lane & 7)) * ROWB
                        + ((lane >> 3) & 1) * 16;

    float acc[4][8][4];
#pragma unroll
    for (int i = 0; i < 4; i++)
#pragma unroll
        for (int j = 0; j < 8; j++)
#pragma unroll
            for (int r = 0; r < 4; r++) acc[i][j][r] = 0.0f;

    constexpr int ITERS = KDIM / BK;

#define FILL_STAGE(stageptr, kbase)                                                   \
    do {                                                                              \
        const uint32_t _st = (stageptr);                                              \
        const int _k0 = (kbase);                                                      \
        _Pragma("unroll")                                                             \
        for (int j = 0; j < 4; j++)                                                   \
            cp16(_st + acd + j * (32 * ROWB), At + acs + (size_t)j * 32 * KDIM + _k0);\
        _Pragma("unroll")                                                             \
        for (int j = 0; j < 8; j++)                                                   \
            cp16(_st + A_BYTES + acd + j * (32 * ROWB),                               \
                 Wt + acs + (size_t)j * 32 * KDIM + _k0);                             \
        asm volatile("cp.async.commit_group;" ::: "memory");                          \
    } while (0)

#define LDFRAG(buf, stbase, k8)                                                       \
    do {                                                                              \
        _Pragma("unroll")                                                             \
        for (int mi = 0; mi < 4; mi++) {                                              \
            ldsm4(af[buf][mi], (stbase) + aoff + mi * (16 * ROWB) + (k8) * 32);       \
            rnd4(af[buf][mi]);                                                        \
        }                                                                             \
        _Pragma("unroll")                                                             \
        for (int n2 = 0; n2 < 4; n2++) {                                              \
            ldsm4(bf[buf][n2], (stbase) + boff + n2 * (16 * ROWB) + (k8) * 32);       \
            rnd4(bf[buf][n2]);                                                        \
        }                                                                             \
    } while (0)

#define MMA_STEP(buf)                                                                 \
    do {                                                                              \
        _Pragma("unroll")                                                             \
        for (int mi = 0; mi < 4; mi++)                                                \
            _Pragma("unroll")                                                         \
            for (int ni = 0; ni < 8; ni++)                                            \
                mma8(acc[mi][ni], af[buf][mi], bf[buf][ni >> 1][(ni & 1) * 2],        \
                     bf[buf][ni >> 1][(ni & 1) * 2 + 1]);                             \
    } while (0)

    // ---- prologue: fill NSTAGE-1 stages ----
#pragma unroll
    for (int s = 0; s < NSTAGE - 1; ++s)
        FILL_STAGE(sb + s * STAGE_SZ, s * BK);

    asm volatile("cp.async.wait_group %0;" :: "n"(NSTAGE - 2) : "memory");
    __syncthreads();

    uint32_t af[2][4][4], bf[2][4][4];
    LDFRAG(0, sb, 0);   // stage 0, k8=0 into buffer 0

    for (int it = 0; it < ITERS; ++it) {
        const uint32_t st = sb + (it % NSTAGE) * STAGE_SZ;

        // prefetch stage it+NSTAGE-1 (targets ring slot it-1: already consumed)
        const int pre = it + NSTAGE - 1;
        if (pre < ITERS)
            FILL_STAGE(sb + (pre % NSTAGE) * STAGE_SZ, pre * BK);
        else
            asm volatile("cp.async.commit_group;" ::: "memory");

#pragma unroll
        for (int k8 = 0; k8 < 4; k8++) {
            const int cur = k8 & 1;
            const int nxt = cur ^ 1;
            if (k8 < 3) {
                // frag prefetch for next k-step (overlaps with this MMA burst)
                LDFRAG(nxt, st, k8 + 1);
            } else if (it + 1 < ITERS) {
                // stage boundary: rendezvous, then load next stage's k0 so the
                // trailing MMA burst below overlaps those LDSMs.
                asm volatile("cp.async.wait_group %0;" :: "n"(NSTAGE - 2) : "memory");
                __syncthreads();
                LDFRAG(nxt, sb + ((it + 1) % NSTAGE) * STAGE_SZ, 0);
            }
            MMA_STEP(cur);
        }
    }
#undef FILL_STAGE
#undef LDFRAG
#undef MMA_STEP

    // ---- epilogue: +bias (+relu); store raw f32 (rounding happens at load) ----
#pragma unroll
    for (int ni = 0; ni < 8; ni++) {
        const int coll = wn + ni * 8 + 2 * (lane & 3);
        const float bv0 = __ldg(&bias[n0g + coll]);
        const float bv1 = __ldg(&bias[n0g + coll + 1]);
#pragma unroll
        for (int mi = 0; mi < 4; mi++) {
            const size_t r0 = (size_t)(m0g + wm + mi * 16 + (lane >> 2));
            float v0 = acc[mi][ni][0] + bv0;
            float v1 = acc[mi][ni][1] + bv1;
            float v2 = acc[mi][ni][2] + bv0;
            float v3 = acc[mi][ni][3] + bv1;
            if (RELU) {
                v0 = fmaxf(v0, 0.0f);
                v1 = fmaxf(v1, 0.0f);
                v2 = fmaxf(v2, 0.0f);
                v3 = fmaxf(v3, 0.0f);
            }
            *(float2*)(C + r0 * N + n0 + coll)       = make_float2(v0, v1);
            *(float2*)(C + (r0 + 8) * N + n0 + coll) = make_float2(v2, v3);
        }
    }
}

// ---------------- launch ----------------
extern "C" void kernel_launch(void* const* d_in, const int* in_sizes, int n_in,
                              void* d_out, int out_size) {
    const float* q  = (const float*)d_in[0];
    const float* W0 = (const float*)d_in[1];
    const float* b0 = (const float*)d_in[2];
    const float* W1 = (const float*)d_in[3];
    const float* b1 = (const float*)d_in[4];
    const float* W2 = (const float*)d_in[5];
    const float* b2 = (const float*)d_in[6];
    float* out = (float*)d_out;

    float *h0, *h1;
    cudaGetSymbolAddress((void**)&h0, g_h0);
    cudaGetSymbolAddress((void**)&h1, g_h1);

    cudaFuncSetAttribute(gemm_tf32_pipe<512, true>,
                         cudaFuncAttributeMaxDynamicSharedMemorySize, SMEM_BYTES);
    cudaFuncSetAttribute(gemm_tf32_pipe<1024, true>,
                         cudaFuncAttributeMaxDynamicSharedMemorySize, SMEM_BYTES);
    cudaFuncSetAttribute(gemm_tf32_pipe<1024, false>,
                         cudaFuncAttributeMaxDynamicSharedMemorySize, SMEM_BYTES);

    // L0: h0 = relu(q @ W0^T + b0)      M=4096 N=1024 K=512
    {
        dim3 grid(4096 / BM, 1024 / BN, 8);
        gemm_tf32_pipe<512, true><<<grid, 256, SMEM_BYTES>>>(q, W0, b0, h0, 1024);
    }
    // L1: h1 = relu(h0 @ W1^T + b1)     M=4096 N=1024 K=1024
    {
        dim3 grid(4096 / BM, 1024 / BN, 8);
        gemm_tf32_pipe<1024, true><<<grid, 256, SMEM_BYTES>>>(h0, W1, b1, h1, 1024);
    }
    // L2: out = h1 @ W2^T + b2          M=4096 N=512 K=1024
    {
        dim3 grid(4096 / BM, 512 / BN, 8);
        gemm_tf32_pipe<1024, false><<<grid, 256, SMEM_BYTES>>>(h1, W2, b2, out, 512);
    }
}

// round 16
// speedup vs baseline: 1.0620x; 1.0620x over previous
#include <cuda_runtime.h>
#include <cstdint>
#include <cstddef>

// ---------------------------------------------------------------------------
// LongTermMemoryMLP on sm_103 (legacy tensor path; tcgen05 blocked by the
// harness's compute_103 virtual arch).
// Round 16: BM=128 BN=256 BK=32, 256 thr, warp tile 64x64, m16n8k8.tf32,
// k8-granular frag pipeline. Hybrid tf32 rounding:
//   * weights pre-rounded ONCE (64MB data, ~40us) -> zero B-frag cvt in loop
//   * h0/h1 rounded in the epilogue (free, fused with bias+relu)
//   * q rounded in-fragment, L0 only (16 cvt/LDFRAG in 20% of the FLOPs)
//   L0: [4096x512] @ [1024x512]^T  +b relu   (x8 batches)
//   L1: [4096x1024]@ [1024x1024]^T +b relu
//   L2: [4096x1024]@ [512x1024]^T  +b
// ---------------------------------------------------------------------------

#define BM 128
#define BN 256
#define BK 32
#define NSTAGE 4

#define ROWB 144                        // 128B k-data + 16B pad per smem row
#define A_BYTES (BM * ROWB)             // 18432
#define B_BYTES (BN * ROWB)             // 36864
#define STAGE_SZ (A_BYTES + B_BYTES)    // 55296
#define SMEM_BYTES (NSTAGE * STAGE_SZ)  // 221184

// ---------------- scratch (no allocations allowed) ----------------
__device__ float g_w0[8u * 1024u * 512u];    // tf32-rounded weights
__device__ float g_w1[8u * 1024u * 1024u];
__device__ float g_w2[8u * 512u * 1024u];
__device__ float g_h0[8u * 4096u * 1024u];   // tf32-rounded activations
__device__ float g_h1[8u * 4096u * 1024u];

// ---------------- helpers ----------------
__device__ __forceinline__ uint32_t smem_u32(const void* p) {
    uint32_t a;
    asm("{ .reg .u64 t; cvta.to.shared.u64 t, %1; cvt.u32.u64 %0, t; }" : "=r"(a) : "l"(p));
    return a;
}
__device__ __forceinline__ uint32_t f2tf(float x) {
    uint32_t r;
    asm("cvt.rna.tf32.f32 %0, %1;" : "=r"(r) : "f"(x));
    return r;
}
__device__ __forceinline__ void cp16(uint32_t dst, const void* src) {
    asm volatile("cp.async.cg.shared.global [%0], [%1], 16;" :: "r"(dst), "l"(src) : "memory");
}
__device__ __forceinline__ void ldsm4(uint32_t* r, uint32_t addr) {
    asm volatile("ldmatrix.sync.aligned.m8n8.x4.shared.b16 {%0,%1,%2,%3}, [%4];"
                 : "=r"(r[0]), "=r"(r[1]), "=r"(r[2]), "=r"(r[3]) : "r"(addr));
}
__device__ __forceinline__ void rnd4(uint32_t* r) {
    r[0] = f2tf(__uint_as_float(r[0]));
    r[1] = f2tf(__uint_as_float(r[1]));
    r[2] = f2tf(__uint_as_float(r[2]));
    r[3] = f2tf(__uint_as_float(r[3]));
}
__device__ __forceinline__ void mma8(float* acc, const uint32_t* a, uint32_t b0, uint32_t b1) {
    asm("mma.sync.aligned.m16n8k8.row.col.f32.tf32.tf32.f32 "
        "{%0,%1,%2,%3}, {%4,%5,%6,%7}, {%8,%9}, {%0,%1,%2,%3};"
        : "+f"(acc[0]), "+f"(acc[1]), "+f"(acc[2]), "+f"(acc[3])
        : "r"(a[0]), "r"(a[1]), "r"(a[2]), "r"(a[3]), "r"(b0), "r"(b1));
}

// ---------------- main GEMM kernel ----------------
// RNDA: rna-round A fragments in-register (only needed when A is raw fp32).
template <int KDIM, bool RELU, bool RNDA>
__global__ __launch_bounds__(256, 1)
void gemm_tf32_pipe(const float* __restrict__ A,     // [B*4096, KDIM]
                    const float* __restrict__ W,     // [B*N, KDIM] tf32-rounded
                    const float* __restrict__ bias,  // [B*N]
                    float* __restrict__ C,           // [B*4096, N]
                    int N) {
    extern __shared__ char smem[];
    const uint32_t sb = smem_u32(smem);

    const int tid  = threadIdx.x;
    const int lane = tid & 31;
    const int warp = tid >> 5;
    const int wm   = (warp & 1) * 64;
    const int wn   = (warp >> 1) * 64;

    const int bz  = blockIdx.z;
    const int m0g = bz * 4096 + blockIdx.x * BM;
    const int n0  = blockIdx.y * BN;
    const int n0g = bz * N + n0;

    const float* At = A + (size_t)m0g * KDIM;
    const float* Wt = W + (size_t)n0g * KDIM;

    // cp.async mapping: rows have 8 chunks of 16B. 256 threads.
    const int arow0 = tid >> 3;          // 0..31
    const int akc   = tid & 7;
    const uint32_t acd = (uint32_t)arow0 * ROWB + akc * 16;
    const size_t   acs = (size_t)arow0 * KDIM + akc * 4;

    // ldmatrix base addresses (conflict-free under 144B row stride)
    const uint32_t aoff = (uint32_t)(wm + ((lane >> 3) & 1) * 8 + (lane & 7)) * ROWB
                        + (lane >> 4) * 16;
    const uint32_t boff = A_BYTES
                        + (uint32_t)(wn + (lane >> 4) * 8 + (lane & 7)) * ROWB
                        + ((lane >> 3) & 1) * 16;

    float acc[4][8][4];
#pragma unroll
    for (int i = 0; i < 4; i++)
#pragma unroll
        for (int j = 0; j < 8; j++)
#pragma unroll
            for (int r = 0; r < 4; r++) acc[i][j][r] = 0.0f;

    constexpr int ITERS = KDIM / BK;

#define FILL_STAGE(stageptr, kbase)                                                   \
    do {                                                                              \
        const uint32_t _st = (stageptr);                                              \
        const int _k0 = (kbase);                                                      \
        _Pragma("unroll")                                                             \
        for (int j = 0; j < 4; j++)                                                   \
            cp16(_st + acd + j * (32 * ROWB), At + acs + (size_t)j * 32 * KDIM + _k0);\
        _Pragma("unroll")                                                             \
        for (int j = 0; j < 8; j++)                                                   \
            cp16(_st + A_BYTES + acd + j * (32 * ROWB),                               \
                 Wt + acs + (size_t)j * 32 * KDIM + _k0);                             \
        asm volatile("cp.async.commit_group;" ::: "memory");                          \
    } while (0)

#define LDFRAG(buf, stbase, k8)                                                       \
    do {                                                                              \
        _Pragma("unroll")                                                             \
        for (int mi = 0; mi < 4; mi++) {                                              \
            ldsm4(af[buf][mi], (stbase) + aoff + mi * (16 * ROWB) + (k8) * 32);       \
            if (RNDA) rnd4(af[buf][mi]);                                              \
        }                                                                             \
        _Pragma("unroll")                                                             \
        for (int n2 = 0; n2 < 4; n2++)                                                \
            ldsm4(bf[buf][n2], (stbase) + boff + n2 * (16 * ROWB) + (k8) * 32);       \
    } while (0)

#define MMA_STEP(buf)                                                                 \
    do {                                                                              \
        _Pragma("unroll")                                                             \
        for (int mi = 0; mi < 4; mi++)                                                \
            _Pragma("unroll")                                                         \
            for (int ni = 0; ni < 8; ni++)                                            \
                mma8(acc[mi][ni], af[buf][mi], bf[buf][ni >> 1][(ni & 1) * 2],        \
                     bf[buf][ni >> 1][(ni & 1) * 2 + 1]);                             \
    } while (0)

    // ---- prologue: fill NSTAGE-1 stages ----
#pragma unroll
    for (int s = 0; s < NSTAGE - 1; ++s)
        FILL_STAGE(sb + s * STAGE_SZ, s * BK);

    asm volatile("cp.async.wait_group %0;" :: "n"(NSTAGE - 2) : "memory");
    __syncthreads();

    uint32_t af[2][4][4], bf[2][4][4];
    LDFRAG(0, sb, 0);   // stage 0, k8=0 into buffer 0

    for (int it = 0; it < ITERS; ++it) {
        const uint32_t st = sb + (it % NSTAGE) * STAGE_SZ;

        // prefetch stage it+NSTAGE-1 (targets ring slot it-1: already consumed)
        const int pre = it + NSTAGE - 1;
        if (pre < ITERS)
            FILL_STAGE(sb + (pre % NSTAGE) * STAGE_SZ, pre * BK);
        else
            asm volatile("cp.async.commit_group;" ::: "memory");

#pragma unroll
        for (int k8 = 0; k8 < 4; k8++) {
            const int cur = k8 & 1;
            const int nxt = cur ^ 1;
            if (k8 < 3) {
                LDFRAG(nxt, st, k8 + 1);   // overlaps with this MMA burst
            } else if (it + 1 < ITERS) {
                asm volatile("cp.async.wait_group %0;" :: "n"(NSTAGE - 2) : "memory");
                __syncthreads();
                LDFRAG(nxt, sb + ((it + 1) % NSTAGE) * STAGE_SZ, 0);
            }
            MMA_STEP(cur);
        }
    }
#undef FILL_STAGE
#undef LDFRAG
#undef MMA_STEP

    // ---- epilogue: +bias, relu + rna-round for intermediate activations ----
#pragma unroll
    for (int ni = 0; ni < 8; ni++) {
        const int coll = wn + ni * 8 + 2 * (lane & 3);
        const float bv0 = __ldg(&bias[n0g + coll]);
        const float bv1 = __ldg(&bias[n0g + coll + 1]);
#pragma unroll
        for (int mi = 0; mi < 4; mi++) {
            const size_t r0 = (size_t)(m0g + wm + mi * 16 + (lane >> 2));
            float v0 = acc[mi][ni][0] + bv0;
            float v1 = acc[mi][ni][1] + bv1;
            float v2 = acc[mi][ni][2] + bv0;
            float v3 = acc[mi][ni][3] + bv1;
            if (RELU) {  // relu + rna-round: consumer reads pre-rounded A
                v0 = __uint_as_float(f2tf(fmaxf(v0, 0.0f)));
                v1 = __uint_as_float(f2tf(fmaxf(v1, 0.0f)));
                v2 = __uint_as_float(f2tf(fmaxf(v2, 0.0f)));
                v3 = __uint_as_float(f2tf(fmaxf(v3, 0.0f)));
            }
            *(float2*)(C + r0 * N + n0 + coll)       = make_float2(v0, v1);
            *(float2*)(C + (r0 + 8) * N + n0 + coll) = make_float2(v2, v3);
        }
    }
}

// ---------------- weight-only tf32 pre-rounding (one launch) ----------------
__global__ void __launch_bounds__(256)
round_w_kernel(const float4* W0, float4* w0,
               const float4* W1, float4* w1,
               const float4* W2, float4* w2) {
    const int which = blockIdx.y;
    const float4* in;
    float4* out;
    int n4;
    if (which == 0)      { in = W0; out = w0; n4 = 8 * 1024 * 512 / 4; }
    else if (which == 1) { in = W1; out = w1; n4 = 8 * 1024 * 1024 / 4; }
    else                 { in = W2; out = w2; n4 = 8 * 512 * 1024 / 4; }
    const int i = blockIdx.x * blockDim.x + threadIdx.x;
    if (i < n4) {
        float4 v = in[i];
        v.x = __uint_as_float(f2tf(v.x));
        v.y = __uint_as_float(f2tf(v.y));
        v.z = __uint_as_float(f2tf(v.z));
        v.w = __uint_as_float(f2tf(v.w));
        out[i] = v;
    }
}

// ---------------- launch ----------------
extern "C" void kernel_launch(void* const* d_in, const int* in_sizes, int n_in,
                              void* d_out, int out_size) {
    const float* q  = (const float*)d_in[0];
    const float* W0 = (const float*)d_in[1];
    const float* b0 = (const float*)d_in[2];
    const float* W1 = (const float*)d_in[3];
    const float* b1 = (const float*)d_in[4];
    const float* W2 = (const float*)d_in[5];
    const float* b2 = (const float*)d_in[6];
    float* out = (float*)d_out;

    float *w0, *w1, *w2, *h0, *h1;
    cudaGetSymbolAddress((void**)&w0, g_w0);
    cudaGetSymbolAddress((void**)&w1, g_w1);
    cudaGetSymbolAddress((void**)&w2, g_w2);
    cudaGetSymbolAddress((void**)&h0, g_h0);
    cudaGetSymbolAddress((void**)&h1, g_h1);

    cudaFuncSetAttribute(gemm_tf32_pipe<512, true, true>,
                         cudaFuncAttributeMaxDynamicSharedMemorySize, SMEM_BYTES);
    cudaFuncSetAttribute(gemm_tf32_pipe<1024, true, false>,
                         cudaFuncAttributeMaxDynamicSharedMemorySize, SMEM_BYTES);
    cudaFuncSetAttribute(gemm_tf32_pipe<1024, false, false>,
                         cudaFuncAttributeMaxDynamicSharedMemorySize, SMEM_BYTES);

    // pre-round weights only (64MB data) in one launch
    {
        dim3 grid(8 * 1024 * 1024 / 4 / 256, 3);   // sized for largest (W1)
        round_w_kernel<<<grid, 256>>>((const float4*)W0, (float4*)w0,
                                      (const float4*)W1, (float4*)w1,
                                      (const float4*)W2, (float4*)w2);
    }

    // L0: h0 = relu(q @ W0^T + b0)   A=q raw -> RNDA=true
    {
        dim3 grid(4096 / BM, 1024 / BN, 8);
        gemm_tf32_pipe<512, true, true><<<grid, 256, SMEM_BYTES>>>(q, w0, b0, h0, 1024);
    }
    // L1: h1 = relu(h0 @ W1^T + b1)  A=h0 pre-rounded -> RNDA=false
    {
        dim3 grid(4096 / BM, 1024 / BN, 8);
        gemm_tf32_pipe<1024, true, false><<<grid, 256, SMEM_BYTES>>>(h0, w1, b1, h1, 1024);
    }
    // L2: out = h1 @ W2^T + b2       A=h1 pre-rounded -> RNDA=false
    {
        dim3 grid(4096 / BM, 512 / BN, 8);
        gemm_tf32_pipe<1024, false, false><<<grid, 256, SMEM_BYTES>>>(h1, w2, b2, out, 512);
    }
}

// round 17
// speedup vs baseline: 1.1909x; 1.1213x over previous
#include <cuda_runtime.h>
#include <cstdint>
#include <cstddef>

// ---------------------------------------------------------------------------
// LongTermMemoryMLP on sm_103 (legacy tensor path; tcgen05 blocked by the
// harness's compute_103 virtual arch).
// Round 17: BM=128 BN=128 BK=32, 128 thr (4 warps, 2x2, warp tile 64x64),
// NSTAGE=3 cp.async ring -> 108KB smem/CTA -> TWO independent CTAs per SM.
// The two CTAs' barriers interleave: one CTA's warps cover the other's
// wait_group/syncthreads drain, keeping the HMMA pipe fed.
// Hybrid tf32 rounding (weights pre-round / epilogue round / L0 in-frag).
//   L0: [4096x512] @ [1024x512]^T  +b relu   (x8 batches)
//   L1: [4096x1024]@ [1024x1024]^T +b relu
//   L2: [4096x1024]@ [512x1024]^T  +b
// ---------------------------------------------------------------------------

#define BM 128
#define BN 128
#define BK 32
#define NSTAGE 3

#define ROWB 144                        // 128B k-data + 16B pad per smem row
#define A_BYTES (BM * ROWB)             // 18432
#define B_BYTES (BN * ROWB)             // 18432
#define STAGE_SZ (A_BYTES + B_BYTES)    // 36864
#define SMEM_BYTES (NSTAGE * STAGE_SZ)  // 110592 per CTA -> 2 CTAs/SM

// ---------------- scratch (no allocations allowed) ----------------
__device__ float g_w0[8u * 1024u * 512u];    // tf32-rounded weights
__device__ float g_w1[8u * 1024u * 1024u];
__device__ float g_w2[8u * 512u * 1024u];
__device__ float g_h0[8u * 4096u * 1024u];   // tf32-rounded activations
__device__ float g_h1[8u * 4096u * 1024u];

// ---------------- helpers ----------------
__device__ __forceinline__ uint32_t smem_u32(const void* p) {
    uint32_t a;
    asm("{ .reg .u64 t; cvta.to.shared.u64 t, %1; cvt.u32.u64 %0, t; }" : "=r"(a) : "l"(p));
    return a;
}
__device__ __forceinline__ uint32_t f2tf(float x) {
    uint32_t r;
    asm("cvt.rna.tf32.f32 %0, %1;" : "=r"(r) : "f"(x));
    return r;
}
__device__ __forceinline__ void cp16(uint32_t dst, const void* src) {
    asm volatile("cp.async.cg.shared.global [%0], [%1], 16;" :: "r"(dst), "l"(src) : "memory");
}
__device__ __forceinline__ void ldsm4(uint32_t* r, uint32_t addr) {
    asm volatile("ldmatrix.sync.aligned.m8n8.x4.shared.b16 {%0,%1,%2,%3}, [%4];"
                 : "=r"(r[0]), "=r"(r[1]), "=r"(r[2]), "=r"(r[3]) : "r"(addr));
}
__device__ __forceinline__ void rnd4(uint32_t* r) {
    r[0] = f2tf(__uint_as_float(r[0]));
    r[1] = f2tf(__uint_as_float(r[1]));
    r[2] = f2tf(__uint_as_float(r[2]));
    r[3] = f2tf(__uint_as_float(r[3]));
}
__device__ __forceinline__ void mma8(float* acc, const uint32_t* a, uint32_t b0, uint32_t b1) {
    asm("mma.sync.aligned.m16n8k8.row.col.f32.tf32.tf32.f32 "
        "{%0,%1,%2,%3}, {%4,%5,%6,%7}, {%8,%9}, {%0,%1,%2,%3};"
        : "+f"(acc[0]), "+f"(acc[1]), "+f"(acc[2]), "+f"(acc[3])
        : "r"(a[0]), "r"(a[1]), "r"(a[2]), "r"(a[3]), "r"(b0), "r"(b1));
}

// ---------------- main GEMM kernel ----------------
// RNDA: rna-round A fragments in-register (only when A is raw fp32 = L0).
template <int KDIM, bool RELU, bool RNDA>
__global__ __launch_bounds__(128, 2)
void gemm_tf32_2cta(const float* __restrict__ A,     // [B*4096, KDIM]
                    const float* __restrict__ W,     // [B*N, KDIM] tf32-rounded
                    const float* __restrict__ bias,  // [B*N]
                    float* __restrict__ C,           // [B*4096, N]
                    int N) {
    extern __shared__ char smem[];
    const uint32_t sb = smem_u32(smem);

    const int tid  = threadIdx.x;
    const int lane = tid & 31;
    const int warp = tid >> 5;          // 0..3
    const int wm   = (warp & 1) * 64;
    const int wn   = (warp >> 1) * 64;

    const int bz  = blockIdx.z;
    const int m0g = bz * 4096 + blockIdx.x * BM;
    const int n0  = blockIdx.y * BN;
    const int n0g = bz * N + n0;

    const float* At = A + (size_t)m0g * KDIM;
    const float* Wt = W + (size_t)n0g * KDIM;

    // cp.async mapping: 128 rows x 8 chunks(16B) each for A and B; 128 thr
    // -> 8 chunks/thread for A, 8 for B.
    const int arow0 = tid >> 3;          // 0..15
    const int akc   = tid & 7;
    const uint32_t acd = (uint32_t)arow0 * ROWB + akc * 16;
    const size_t   acs = (size_t)arow0 * KDIM + akc * 4;

    // ldmatrix base addresses (conflict-free under 144B row stride)
    const uint32_t aoff = (uint32_t)(wm + ((lane >> 3) & 1) * 8 + (lane & 7)) * ROWB
                        + (lane >> 4) * 16;
    const uint32_t boff = A_BYTES
                        + (uint32_t)(wn + (lane >> 4) * 8 + (lane & 7)) * ROWB
                        + ((lane >> 3) & 1) * 16;

    float acc[4][8][4];
#pragma unroll
    for (int i = 0; i < 4; i++)
#pragma unroll
        for (int j = 0; j < 8; j++)
#pragma unroll
            for (int r = 0; r < 4; r++) acc[i][j][r] = 0.0f;

    constexpr int ITERS = KDIM / BK;

#define FILL_STAGE(stageptr, kbase)                                                   \
    do {                                                                              \
        const uint32_t _st = (stageptr);                                              \
        const int _k0 = (kbase);                                                      \
        _Pragma("unroll")                                                             \
        for (int j = 0; j < 8; j++)                                                   \
            cp16(_st + acd + j * (16 * ROWB), At + acs + (size_t)j * 16 * KDIM + _k0);\
        _Pragma("unroll")                                                             \
        for (int j = 0; j < 8; j++)                                                   \
            cp16(_st + A_BYTES + acd + j * (16 * ROWB),                               \
                 Wt + acs + (size_t)j * 16 * KDIM + _k0);                             \
        asm volatile("cp.async.commit_group;" ::: "memory");                          \
    } while (0)

#define LDFRAG(buf, stbase, k8)                                                       \
    do {                                                                              \
        _Pragma("unroll")                                                             \
        for (int mi = 0; mi < 4; mi++) {                                              \
            ldsm4(af[buf][mi], (stbase) + aoff + mi * (16 * ROWB) + (k8) * 32);       \
            if (RNDA) rnd4(af[buf][mi]);                                              \
        }                                                                             \
        _Pragma("unroll")                                                             \
        for (int n2 = 0; n2 < 4; n2++)                                                \
            ldsm4(bf[buf][n2], (stbase) + boff + n2 * (16 * ROWB) + (k8) * 32);       \
    } while (0)

#define MMA_STEP(buf)                                                                 \
    do {                                                                              \
        _Pragma("unroll")                                                             \
        for (int mi = 0; mi < 4; mi++)                                                \
            _Pragma("unroll")                                                         \
            for (int ni = 0; ni < 8; ni++)                                            \
                mma8(acc[mi][ni], af[buf][mi], bf[buf][ni >> 1][(ni & 1) * 2],        \
                     bf[buf][ni >> 1][(ni & 1) * 2 + 1]);                             \
    } while (0)

    // ---- prologue: fill NSTAGE-1 stages ----
#pragma unroll
    for (int s = 0; s < NSTAGE - 1; ++s)
        FILL_STAGE(sb + s * STAGE_SZ, s * BK);

    asm volatile("cp.async.wait_group %0;" :: "n"(NSTAGE - 2) : "memory");
    __syncthreads();

    uint32_t af[2][4][4], bf[2][4][4];
    LDFRAG(0, sb, 0);   // stage 0, k8=0 into buffer 0

    for (int it = 0; it < ITERS; ++it) {
        const uint32_t st = sb + (it % NSTAGE) * STAGE_SZ;

        // prefetch stage it+NSTAGE-1 (targets ring slot it-1: already consumed)
        const int pre = it + NSTAGE - 1;
        if (pre < ITERS)
            FILL_STAGE(sb + (pre % NSTAGE) * STAGE_SZ, pre * BK);
        else
            asm volatile("cp.async.commit_group;" ::: "memory");

#pragma unroll
        for (int k8 = 0; k8 < 4; k8++) {
            const int cur = k8 & 1;
            const int nxt = cur ^ 1;
            if (k8 < 3) {
                LDFRAG(nxt, st, k8 + 1);   // overlaps with this MMA burst
            } else if (it + 1 < ITERS) {
                asm volatile("cp.async.wait_group %0;" :: "n"(NSTAGE - 2) : "memory");
                __syncthreads();
                LDFRAG(nxt, sb + ((it + 1) % NSTAGE) * STAGE_SZ, 0);
            }
            MMA_STEP(cur);
        }
    }
#undef FILL_STAGE
#undef LDFRAG
#undef MMA_STEP

    // ---- epilogue: +bias, relu + rna-round for intermediate activations ----
#pragma unroll
    for (int ni = 0; ni < 8; ni++) {
        const int coll = wn + ni * 8 + 2 * (lane & 3);
        const float bv0 = __ldg(&bias[n0g + coll]);
        const float bv1 = __ldg(&bias[n0g + coll + 1]);
#pragma unroll
        for (int mi = 0; mi < 4; mi++) {
            const size_t r0 = (size_t)(m0g + wm + mi * 16 + (lane >> 2));
            float v0 = acc[mi][ni][0] + bv0;
            float v1 = acc[mi][ni][1] + bv1;
            float v2 = acc[mi][ni][2] + bv0;
            float v3 = acc[mi][ni][3] + bv1;
            if (RELU) {  // relu + rna-round: consumer reads pre-rounded A
                v0 = __uint_as_float(f2tf(fmaxf(v0, 0.0f)));
                v1 = __uint_as_float(f2tf(fmaxf(v1, 0.0f)));
                v2 = __uint_as_float(f2tf(fmaxf(v2, 0.0f)));
                v3 = __uint_as_float(f2tf(fmaxf(v3, 0.0f)));
            }
            *(float2*)(C + r0 * N + n0 + coll)       = make_float2(v0, v1);
            *(float2*)(C + (r0 + 8) * N + n0 + coll) = make_float2(v2, v3);
        }
    }
}

// ---------------- weight-only tf32 pre-rounding (one launch) ----------------
__global__ void __launch_bounds__(256)
round_w_kernel(const float4* W0, float4* w0,
               const float4* W1, float4* w1,
               const float4* W2, float4* w2) {
    const int which = blockIdx.y;
    const float4* in;
    float4* out;
    int n4;
    if (which == 0)      { in = W0; out = w0; n4 = 8 * 1024 * 512 / 4; }
    else if (which == 1) { in = W1; out = w1; n4 = 8 * 1024 * 1024 / 4; }
    else                 { in = W2; out = w2; n4 = 8 * 512 * 1024 / 4; }
    const int i = blockIdx.x * blockDim.x + threadIdx.x;
    if (i < n4) {
        float4 v = in[i];
        v.x = __uint_as_float(f2tf(v.x));
        v.y = __uint_as_float(f2tf(v.y));
        v.z = __uint_as_float(f2tf(v.z));
        v.w = __uint_as_float(f2tf(v.w));
        out[i] = v;
    }
}

// ---------------- launch ----------------
extern "C" void kernel_launch(void* const* d_in, const int* in_sizes, int n_in,
                              void* d_out, int out_size) {
    const float* q  = (const float*)d_in[0];
    const float* W0 = (const float*)d_in[1];
    const float* b0 = (const float*)d_in[2];
    const float* W1 = (const float*)d_in[3];
    const float* b1 = (const float*)d_in[4];
    const float* W2 = (const float*)d_in[5];
    const float* b2 = (const float*)d_in[6];
    float* out = (float*)d_out;

    float *w0, *w1, *w2, *h0, *h1;
    cudaGetSymbolAddress((void**)&w0, g_w0);
    cudaGetSymbolAddress((void**)&w1, g_w1);
    cudaGetSymbolAddress((void**)&w2, g_w2);
    cudaGetSymbolAddress((void**)&h0, g_h0);
    cudaGetSymbolAddress((void**)&h1, g_h1);

    cudaFuncSetAttribute(gemm_tf32_2cta<512, true, true>,
                         cudaFuncAttributeMaxDynamicSharedMemorySize, SMEM_BYTES);
    cudaFuncSetAttribute(gemm_tf32_2cta<1024, true, false>,
                         cudaFuncAttributeMaxDynamicSharedMemorySize, SMEM_BYTES);
    cudaFuncSetAttribute(gemm_tf32_2cta<1024, false, false>,
                         cudaFuncAttributeMaxDynamicSharedMemorySize, SMEM_BYTES);

    // pre-round weights only (64MB data) in one launch
    {
        dim3 grid(8 * 1024 * 1024 / 4 / 256, 3);   // sized for largest (W1)
        round_w_kernel<<<grid, 256>>>((const float4*)W0, (float4*)w0,
                                      (const float4*)W1, (float4*)w1,
                                      (const float4*)W2, (float4*)w2);
    }

    // L0: h0 = relu(q @ W0^T + b0)   A=q raw -> RNDA=true
    {
        dim3 grid(4096 / BM, 1024 / BN, 8);
        gemm_tf32_2cta<512, true, true><<<grid, 128, SMEM_BYTES>>>(q, w0, b0, h0, 1024);
    }
    // L1: h1 = relu(h0 @ W1^T + b1)
    {
        dim3 grid(4096 / BM, 1024 / BN, 8);
        gemm_tf32_2cta<1024, true, false><<<grid, 128, SMEM_BYTES>>>(h0, w1, b1, h1, 1024);
    }
    // L2: out = h1 @ W2^T + b2
    {
        dim3 grid(4096 / BM, 512 / BN, 8);
        gemm_tf32_2cta<1024, false, false><<<grid, 128, SMEM_BYTES>>>(h1, w2, b2, out, 512);
    }
}